// round 13
// baseline (speedup 1.0000x reference)
#include <cuda_runtime.h>
#include <cuda_fp16.h>

// RestrictedNN GB300. B=4096, NINP=4096, L0=512(G=8,H=16), L1=64, L2=8.
// k1 (R11 structure, 2 rows/lane): x -> gene-folded -> h0 -> h1.
//    h0 via tanh.approx with affine folded into w1s/bias1 staging.
//    h1: exact ex2/rcp sigmoid, stored ROW-MAJOR fp16: g_h1c[row][1024].
// k2: 512 thr, 16 rows/block, grid 256. warp=(module m, feature-half fh);
//    lane=(row, feature-quarter q). Acts: 4 contiguous LDG.128 per lane.
//    SCALE folded into activations; W2 staged raw; W3 via __ldg.

#define SCALE (-1.44269504f)

typedef unsigned long long u64;

__device__ __half g_h1c[(size_t)4096 * 1024];   // [row][feature], 8 MB

__device__ __forceinline__ u64 pack2(float lo, float hi) {
    u64 r; asm("mov.b64 %0, {%1, %2};" : "=l"(r) : "f"(lo), "f"(hi)); return r;
}
__device__ __forceinline__ void unpack2(u64 v, float& lo, float& hi) {
    asm("mov.b64 {%0, %1}, %2;" : "=f"(lo), "=f"(hi) : "l"(v));
}
__device__ __forceinline__ u64 ffma2(u64 a, u64 b, u64 c) {
    u64 d; asm("fma.rn.f32x2 %0, %1, %2, %3;" : "=l"(d) : "l"(a), "l"(b), "l"(c));
    return d;
}
__device__ __forceinline__ u64 add2(u64 a, u64 b) {
    u64 d; asm("add.rn.f32x2 %0, %1, %2;" : "=l"(d) : "l"(a), "l"(b));
    return d;
}
__device__ __forceinline__ float tanhap(float z) {
    float t; asm("tanh.approx.f32 %0, %1;" : "=f"(t) : "f"(z)); return t;
}
__device__ __forceinline__ u64 sig2s(u64 z) {          // z pre-scaled by -log2e
    float a, b; unpack2(z, a, b);
    float ea, eb, ra, rb;
    asm("ex2.approx.f32 %0, %1;" : "=f"(ea) : "f"(a));
    asm("ex2.approx.f32 %0, %1;" : "=f"(eb) : "f"(b));
    asm("rcp.approx.f32 %0, %1;" : "=f"(ra) : "f"(1.0f + ea));
    asm("rcp.approx.f32 %0, %1;" : "=f"(rb) : "f"(1.0f + eb));
    return pack2(ra, rb);
}

// ---------------------------------------------------------------------------
// K1: grid (8 tile-groups, 64 g), 256 threads = 8 warps; warp -> one 64-row
// tile. Lane p handles rows (tile*64+p, tile*64+p+32). 2 blocks/SM.
// ---------------------------------------------------------------------------
__global__ __launch_bounds__(256, 2) void k1(
    const float* __restrict__ x, const float* __restrict__ Wg,
    const float* __restrict__ bgp, const float* __restrict__ W0,
    const float* __restrict__ W1)
{
    __shared__ __align__(16) float w0ps[1024];    // [l][j][h] * Wg * 0.5
    __shared__ __align__(16) float bias0s[128];   // [l][h] * 0.5
    __shared__ __align__(16) float w1s[2048];     // [k][h] * 0.5 * SCALE
    __shared__ __align__(16) float bias1s[16];    // 0.5*SCALE*sum_k W1[k][h]

    const int g   = blockIdx.y;
    const int tid = threadIdx.x;

    {
        float4 v = ((const float4*)(W0 + (size_t)g * 1024))[tid];
        float wg = Wg[g * 64 + (tid >> 2)] * 0.5f;
        float4 o; o.x = v.x * wg; o.y = v.y * wg; o.z = v.z * wg; o.w = v.w * wg;
        ((float4*)w0ps)[tid] = o;
    }
    #pragma unroll
    for (int it = 0; it < 2; ++it) {
        int i4 = tid + 256 * it;
        float4 v = ((const float4*)(W1 + (size_t)g * 2048))[i4];
        const float s = 0.5f * SCALE;
        float4 o; o.x = v.x * s; o.y = v.y * s; o.z = v.z * s; o.w = v.w * s;
        ((float4*)w1s)[i4] = o;
    }
    if (tid < 128) {
        int l = tid >> 4, h = tid & 15;
        const float* bgl = bgp + g * 64 + l * 8;
        const float* w0l = W0 + (size_t)g * 1024 + l * 128 + h;
        float a = 0.f;
        #pragma unroll
        for (int j = 0; j < 8; ++j) a += bgl[j] * w0l[j * 16];
        bias0s[tid] = a * 0.5f;
    }
    __syncthreads();
    if (tid < 16) {
        float a = 0.f;
        for (int k = 0; k < 128; ++k) a += w1s[k * 16 + tid];  // already scaled
        bias1s[tid] = a;
    }
    __syncthreads();

    const int warp = tid >> 5, lane = tid & 31;
    const int tile = blockIdx.x * 8 + warp;
    const int rA = tile * 64 + lane;
    const int rB = rA + 32;
    const float* xA = x + (size_t)rA * 4096 + g * 64;
    const float* xB = x + (size_t)rB * 4096 + g * 64;

    u64 acc1[2][8];
    #pragma unroll
    for (int hp = 0; hp < 8; ++hp) {
        u64 b = ((const u64*)bias1s)[hp];
        acc1[0][hp] = b; acc1[1][hp] = b;
    }

    float4 pa0 = __ldg((const float4*)xA), pa1 = __ldg((const float4*)xA + 1);
    float4 pb0 = __ldg((const float4*)xB), pb1 = __ldg((const float4*)xB + 1);

    #pragma unroll 1
    for (int l = 0; l < 8; ++l) {
        float xa[8], xb[8];
        xa[0]=pa0.x; xa[1]=pa0.y; xa[2]=pa0.z; xa[3]=pa0.w;
        xa[4]=pa1.x; xa[5]=pa1.y; xa[6]=pa1.z; xa[7]=pa1.w;
        xb[0]=pb0.x; xb[1]=pb0.y; xb[2]=pb0.z; xb[3]=pb0.w;
        xb[4]=pb1.x; xb[5]=pb1.y; xb[6]=pb1.z; xb[7]=pb1.w;
        {
            int ln = (l + 1) & 7;
            pa0 = __ldg((const float4*)(xA + ln * 8));
            pa1 = __ldg((const float4*)(xA + ln * 8) + 1);
            pb0 = __ldg((const float4*)(xB + ln * 8));
            pb1 = __ldg((const float4*)(xB + ln * 8) + 1);
        }

        u64 acc0[2][8];
        #pragma unroll
        for (int hp = 0; hp < 8; ++hp) {
            u64 b = ((const u64*)bias0s)[l * 8 + hp];
            acc0[0][hp] = b; acc0[1][hp] = b;
        }
        #pragma unroll
        for (int j = 0; j < 8; ++j) {
            u64 dA = pack2(xa[j], xa[j]);
            u64 dB = pack2(xb[j], xb[j]);
            const ulonglong2* wrow = (const ulonglong2*)(w0ps + l * 128 + j * 16);
            #pragma unroll
            for (int hq = 0; hq < 4; ++hq) {
                ulonglong2 w = wrow[hq];                 // broadcast
                acc0[0][hq*2]   = ffma2(dA, w.x, acc0[0][hq*2]);
                acc0[0][hq*2+1] = ffma2(dA, w.y, acc0[0][hq*2+1]);
                acc0[1][hq*2]   = ffma2(dB, w.x, acc0[1][hq*2]);
                acc0[1][hq*2+1] = ffma2(dB, w.y, acc0[1][hq*2+1]);
            }
        }

        // tanh(h0/2) -> accumulate into h1; tanh first, weights streamed
        #pragma unroll
        for (int hp = 0; hp < 8; ++hp) {
            u64 dk0[2], dk1[2];
            #pragma unroll
            for (int r = 0; r < 2; ++r) {
                float a0, a1; unpack2(acc0[r][hp], a0, a1);
                float t0 = tanhap(a0), t1 = tanhap(a1);
                dk0[r] = pack2(t0, t0); dk1[r] = pack2(t1, t1);
            }
            const int k0 = l * 16 + hp * 2;
            const ulonglong2* wr0 = (const ulonglong2*)(w1s + k0 * 16);
            const ulonglong2* wr1 = (const ulonglong2*)(w1s + (k0 + 1) * 16);
            #pragma unroll
            for (int c = 0; c < 4; ++c) {
                ulonglong2 A = wr0[c];
                ulonglong2 B = wr1[c];
                #pragma unroll
                for (int r = 0; r < 2; ++r) {
                    acc1[r][c*2]   = ffma2(dk0[r], A.x, acc1[r][c*2]);
                    acc1[r][c*2+1] = ffma2(dk0[r], A.y, acc1[r][c*2+1]);
                    acc1[r][c*2]   = ffma2(dk1[r], B.x, acc1[r][c*2]);
                    acc1[r][c*2+1] = ffma2(dk1[r], B.y, acc1[r][c*2+1]);
                }
            }
        }
    }

    // finalize h1: exact sigmoid, store ROW-MAJOR fp16 (2x STG.128 per row)
    #pragma unroll
    for (int r = 0; r < 2; ++r) {
        const int row = r ? rB : rA;
        unsigned int o[8];
        #pragma unroll
        for (int hp = 0; hp < 8; ++hp) {
            u64 s = sig2s(acc1[r][hp]);
            float s0, s1; unpack2(s, s0, s1);
            __half2 hv = __floats2half2_rn(s0, s1);
            o[hp] = *reinterpret_cast<unsigned int*>(&hv);
        }
        uint4* dst = (uint4*)(g_h1c + (size_t)row * 1024 + g * 16);
        dst[0] = make_uint4(o[0], o[1], o[2], o[3]);
        dst[1] = make_uint4(o[4], o[5], o[6], o[7]);
    }
}

// ---------------------------------------------------------------------------
// K2: grid 256 x 16 rows, 512 threads = 16 warps.
// warp w: module m=w&7, feature-half fh=w>>3. lane: row=lane&15, quarter
// q=lane>>4 -> 32 contiguous features. Acts: 4 LDG.128/lane. SCALE on acts.
// ---------------------------------------------------------------------------
#define H2S_FLOATS (16 * 129 + 4)   // +4 keeps following u64 regions 8B-aligned

__global__ __launch_bounds__(512, 2) void k2(
    const float* __restrict__ W2, const float* __restrict__ W3,
    const float* __restrict__ Wf, float* __restrict__ out)
{
    extern __shared__ __align__(16) unsigned char smraw2[];
    float* w2s   = (float*)smraw2;             // raw W2 [m][k][h], 16384 f
    float* h2s   = w2s + 16384;                // [row][129]
    u64*   part2 = (u64*)(h2s + H2S_FLOATS);   // [hp][m][row] = 8*8*16
    u64*   part  = part2 + 1024;               // [hp][chunk][row] = 8*8*16
    float* fpart = (float*)(part + 1024);      // [w][row] = 8*16

    const int tid  = threadIdx.x;
    const int warp = tid >> 5;
    const int lane = tid & 31;
    const int row  = lane & 15;
    const int q    = lane >> 4;
    const int row0 = blockIdx.x * 16;
    const int m    = warp & 7;
    const int fh   = warp >> 3;
    const int fb   = m * 128 + fh * 64 + q * 32;   // 32 contiguous features

    // stage W2 raw (no scale — SCALE folded into activations)
    #pragma unroll
    for (int it = 0; it < 8; ++it) {
        int i4 = tid + 512 * it;               // 4096 float4
        ((float4*)w2s)[i4] = __ldg((const float4*)W2 + i4);
    }
    __syncthreads();

    // ---- h2 partial: 32 contiguous features, 4x LDG.128 up front ----
    u64 acc[8];
    #pragma unroll
    for (int hp = 0; hp < 8; ++hp) acc[hp] = 0ull;
    {
        const uint4* arow = (const uint4*)(g_h1c + (size_t)(row0 + row) * 1024 + fb);
        uint4 c0 = __ldg(arow), c1 = __ldg(arow + 1);
        uint4 c2 = __ldg(arow + 2), c3 = __ldg(arow + 3);
        unsigned int u[16];
        u[0]=c0.x;  u[1]=c0.y;  u[2]=c0.z;  u[3]=c0.w;
        u[4]=c1.x;  u[5]=c1.y;  u[6]=c1.z;  u[7]=c1.w;
        u[8]=c2.x;  u[9]=c2.y;  u[10]=c2.z; u[11]=c2.w;
        u[12]=c3.x; u[13]=c3.y; u[14]=c3.z; u[15]=c3.w;

        #pragma unroll
        for (int p = 0; p < 16; ++p) {
            __half2 hv = *reinterpret_cast<__half2*>(&u[p]);
            float2 f2 = __half22float2(hv);
            float a0 = f2.x * SCALE, a1 = f2.y * SCALE;
            u64 d0 = pack2(a0, a0), d1 = pack2(a1, a1);
            const int f = fb + p * 2;
            const ulonglong2* wr0 = (const ulonglong2*)(w2s + f * 16);
            const ulonglong2* wr1 = (const ulonglong2*)(w2s + (f + 1) * 16);
            ulonglong2 A0 = wr0[0], A1 = wr0[1], A2 = wr0[2], A3 = wr0[3];
            acc[0] = ffma2(d0, A0.x, acc[0]);
            acc[1] = ffma2(d0, A0.y, acc[1]);
            acc[2] = ffma2(d0, A1.x, acc[2]);
            acc[3] = ffma2(d0, A1.y, acc[3]);
            acc[4] = ffma2(d0, A2.x, acc[4]);
            acc[5] = ffma2(d0, A2.y, acc[5]);
            acc[6] = ffma2(d0, A3.x, acc[6]);
            acc[7] = ffma2(d0, A3.y, acc[7]);
            ulonglong2 B0 = wr1[0], B1 = wr1[1], B2 = wr1[2], B3 = wr1[3];
            acc[0] = ffma2(d1, B0.x, acc[0]);
            acc[1] = ffma2(d1, B0.y, acc[1]);
            acc[2] = ffma2(d1, B1.x, acc[2]);
            acc[3] = ffma2(d1, B1.y, acc[3]);
            acc[4] = ffma2(d1, B2.x, acc[4]);
            acc[5] = ffma2(d1, B2.y, acc[5]);
            acc[6] = ffma2(d1, B3.x, acc[6]);
            acc[7] = ffma2(d1, B3.y, acc[7]);
        }
    }
    // combine feature-quarters within warp
    #pragma unroll
    for (int hp = 0; hp < 8; ++hp)
        acc[hp] = add2(acc[hp], __shfl_xor_sync(0xffffffffu, acc[hp], 16));

    if (warp >= 8 && q == 0) {                 // fh=1 partials -> smem
        #pragma unroll
        for (int hp = 0; hp < 8; ++hp)
            part2[hp * 128 + m * 16 + row] = acc[hp];
    }
    __syncthreads();

    if (warp < 8 && q == 0) {                  // fh=0 combines + sigmoid
        #pragma unroll
        for (int hp = 0; hp < 8; ++hp) {
            u64 s = sig2s(add2(acc[hp], part2[hp * 128 + m * 16 + row]));
            float s0, s1; unpack2(s, s0, s1);
            h2s[row * 129 + m * 16 + hp * 2]     = s0;
            h2s[row * 129 + m * 16 + hp * 2 + 1] = s1;
        }
    }
    __syncthreads();

    // ---- root partial: warp w (<8) covers k-chunk [w*16,(w+1)*16),
    //      q splits it 8/8; W3 via __ldg (L1-resident) ----
    if (warp < 8) {
        u64 racc[8];
        #pragma unroll
        for (int hp = 0; hp < 8; ++hp) racc[hp] = 0ull;
        #pragma unroll
        for (int t = 0; t < 8; ++t) {
            int jg = warp * 16 + q * 8 + t;
            float a = h2s[row * 129 + jg] * SCALE;
            u64 d = pack2(a, a);
            const ulonglong2* wr = (const ulonglong2*)(W3 + jg * 16);
            ulonglong2 w0 = __ldg(wr), w1 = __ldg(wr + 1);
            ulonglong2 w2v = __ldg(wr + 2), w3v = __ldg(wr + 3);
            racc[0] = ffma2(d, w0.x,  racc[0]);
            racc[1] = ffma2(d, w0.y,  racc[1]);
            racc[2] = ffma2(d, w1.x,  racc[2]);
            racc[3] = ffma2(d, w1.y,  racc[3]);
            racc[4] = ffma2(d, w2v.x, racc[4]);
            racc[5] = ffma2(d, w2v.y, racc[5]);
            racc[6] = ffma2(d, w3v.x, racc[6]);
            racc[7] = ffma2(d, w3v.y, racc[7]);
        }
        #pragma unroll
        for (int hp = 0; hp < 8; ++hp)
            racc[hp] = add2(racc[hp], __shfl_xor_sync(0xffffffffu, racc[hp], 16));
        if (q == 0) {
            #pragma unroll
            for (int hp = 0; hp < 8; ++hp)
                part[hp * 128 + warp * 16 + row] = racc[hp];
        }
    }
    __syncthreads();

    // ---- reduce: warp w (<8) owns h-pair hp=w ----
    if (warp < 8 && q == 0) {
        u64 s = part[warp * 128 + row];
        #pragma unroll
        for (int ww = 1; ww < 8; ++ww)
            s = add2(s, part[warp * 128 + ww * 16 + row]);
        u64 sg = sig2s(s);
        float s0, s1; unpack2(sg, s0, s1);
        float c = s0 * __ldg(Wf + warp * 2) + s1 * __ldg(Wf + warp * 2 + 1);
        fpart[warp * 16 + row] = c;
    }
    __syncthreads();

    if (warp == 0 && q == 0) {
        float a = fpart[row];
        #pragma unroll
        for (int ww = 1; ww < 8; ++ww) a += fpart[ww * 16 + row];
        out[row0 + row] = a;
    }
}

static const int K2_SMEM = (16384 + H2S_FLOATS) * 4 + 1024 * 8 + 1024 * 8 + 128 * 4;

extern "C" void kernel_launch(void* const* d_in, const int* in_sizes, int n_in,
                              void* d_out, int out_size)
{
    const float* x  = (const float*)d_in[0];
    const float* Wg = (const float*)d_in[1];
    const float* bg = (const float*)d_in[2];
    const float* W0 = (const float*)d_in[3];
    const float* W1 = (const float*)d_in[4];
    const float* W2 = (const float*)d_in[5];
    const float* W3 = (const float*)d_in[6];
    const float* Wf = (const float*)d_in[7];
    float* out = (float*)d_out;

    cudaFuncSetAttribute(k2, cudaFuncAttributeMaxDynamicSharedMemorySize, K2_SMEM);

    dim3 g1(8, 64);
    k1<<<g1, 256>>>(x, Wg, bg, W0, W1);
    k2<<<256, 512, K2_SMEM>>>(W2, W3, Wf, out);
}

// round 14
// speedup vs baseline: 1.0242x; 1.0242x over previous
#include <cuda_runtime.h>
#include <cuda_fp16.h>

// RestrictedNN GB300. B=4096, NINP=4096, L0=512(G=8,H=16), L1=64, L2=8.
// k1 (R11 body, 128-thr blocks for finer wave quantization): x -> h0 -> h1.
//    h0 via tanh.approx, affine folded into w1s/bias1 staging.
//    h1: exact ex2/rcp sigmoid, stored transposed fp16 g_h1h[feature][row].
// k2 (R11 exact): grid 256 x 16-row blocks, 512 thr; feature-major act reads,
//    warp-uniform smem weights. Launched with PDL: stages weights during k1
//    tail, cudaGridDependencySynchronize() before reading g_h1h.

#define SCALE (-1.44269504f)

typedef unsigned long long u64;

__device__ __half g_h1h[(size_t)1024 * 4096];   // [feature][row], 8 MB

__device__ __forceinline__ u64 pack2(float lo, float hi) {
    u64 r; asm("mov.b64 %0, {%1, %2};" : "=l"(r) : "f"(lo), "f"(hi)); return r;
}
__device__ __forceinline__ void unpack2(u64 v, float& lo, float& hi) {
    asm("mov.b64 {%0, %1}, %2;" : "=f"(lo), "=f"(hi) : "l"(v));
}
__device__ __forceinline__ u64 ffma2(u64 a, u64 b, u64 c) {
    u64 d; asm("fma.rn.f32x2 %0, %1, %2, %3;" : "=l"(d) : "l"(a), "l"(b), "l"(c));
    return d;
}
__device__ __forceinline__ u64 add2(u64 a, u64 b) {
    u64 d; asm("add.rn.f32x2 %0, %1, %2;" : "=l"(d) : "l"(a), "l"(b));
    return d;
}
__device__ __forceinline__ float tanhap(float z) {
    float t; asm("tanh.approx.f32 %0, %1;" : "=f"(t) : "f"(z)); return t;
}
__device__ __forceinline__ u64 sig2s(u64 z) {          // z pre-scaled by -log2e
    float a, b; unpack2(z, a, b);
    float ea, eb, ra, rb;
    asm("ex2.approx.f32 %0, %1;" : "=f"(ea) : "f"(a));
    asm("ex2.approx.f32 %0, %1;" : "=f"(eb) : "f"(b));
    asm("rcp.approx.f32 %0, %1;" : "=f"(ra) : "f"(1.0f + ea));
    asm("rcp.approx.f32 %0, %1;" : "=f"(rb) : "f"(1.0f + eb));
    return pack2(ra, rb);
}

// ---------------------------------------------------------------------------
// K1: grid (16 tile-groups, 64 g), 128 threads = 4 warps; warp -> one 64-row
// tile. Lane p handles rows (tile*64+p, tile*64+p+32). 4 blocks/SM.
// ---------------------------------------------------------------------------
__global__ __launch_bounds__(128, 4) void k1(
    const float* __restrict__ x, const float* __restrict__ Wg,
    const float* __restrict__ bgp, const float* __restrict__ W0,
    const float* __restrict__ W1)
{
    __shared__ __align__(16) float w0ps[1024];    // [l][j][h] * Wg * 0.5
    __shared__ __align__(16) float bias0s[128];   // [l][h] * 0.5
    __shared__ __align__(16) float w1s[2048];     // [k][h] * 0.5 * SCALE
    __shared__ __align__(16) float bias1s[16];    // 0.5*SCALE*sum_k W1[k][h]

    const int g   = blockIdx.y;
    const int tid = threadIdx.x;

    #pragma unroll
    for (int it = 0; it < 2; ++it) {
        int i4 = tid + 128 * it;               // 256 float4
        float4 v = ((const float4*)(W0 + (size_t)g * 1024))[i4];
        float wg = Wg[g * 64 + (i4 >> 2)] * 0.5f;
        float4 o; o.x = v.x * wg; o.y = v.y * wg; o.z = v.z * wg; o.w = v.w * wg;
        ((float4*)w0ps)[i4] = o;
    }
    #pragma unroll
    for (int it = 0; it < 4; ++it) {
        int i4 = tid + 128 * it;               // 512 float4
        float4 v = ((const float4*)(W1 + (size_t)g * 2048))[i4];
        const float s = 0.5f * SCALE;
        float4 o; o.x = v.x * s; o.y = v.y * s; o.z = v.z * s; o.w = v.w * s;
        ((float4*)w1s)[i4] = o;
    }
    {
        int l = tid >> 4, h = tid & 15;        // all 128 threads
        const float* bgl = bgp + g * 64 + l * 8;
        const float* w0l = W0 + (size_t)g * 1024 + l * 128 + h;
        float a = 0.f;
        #pragma unroll
        for (int j = 0; j < 8; ++j) a += bgl[j] * w0l[j * 16];
        bias0s[tid] = a * 0.5f;
    }
    __syncthreads();
    if (tid < 16) {
        float a = 0.f;
        for (int k = 0; k < 128; ++k) a += w1s[k * 16 + tid];  // already scaled
        bias1s[tid] = a;
    }
    __syncthreads();

    const int warp = tid >> 5, lane = tid & 31;
    const int tile = blockIdx.x * 4 + warp;
    const int rA = tile * 64 + lane;
    const int rB = rA + 32;
    const float* xA = x + (size_t)rA * 4096 + g * 64;
    const float* xB = x + (size_t)rB * 4096 + g * 64;

    u64 acc1[2][8];
    #pragma unroll
    for (int hp = 0; hp < 8; ++hp) {
        u64 b = ((const u64*)bias1s)[hp];
        acc1[0][hp] = b; acc1[1][hp] = b;
    }

    float4 pa0 = __ldg((const float4*)xA), pa1 = __ldg((const float4*)xA + 1);
    float4 pb0 = __ldg((const float4*)xB), pb1 = __ldg((const float4*)xB + 1);

    #pragma unroll 1
    for (int l = 0; l < 8; ++l) {
        float xa[8], xb[8];
        xa[0]=pa0.x; xa[1]=pa0.y; xa[2]=pa0.z; xa[3]=pa0.w;
        xa[4]=pa1.x; xa[5]=pa1.y; xa[6]=pa1.z; xa[7]=pa1.w;
        xb[0]=pb0.x; xb[1]=pb0.y; xb[2]=pb0.z; xb[3]=pb0.w;
        xb[4]=pb1.x; xb[5]=pb1.y; xb[6]=pb1.z; xb[7]=pb1.w;
        {
            int ln = (l + 1) & 7;
            pa0 = __ldg((const float4*)(xA + ln * 8));
            pa1 = __ldg((const float4*)(xA + ln * 8) + 1);
            pb0 = __ldg((const float4*)(xB + ln * 8));
            pb1 = __ldg((const float4*)(xB + ln * 8) + 1);
        }

        u64 acc0[2][8];
        #pragma unroll
        for (int hp = 0; hp < 8; ++hp) {
            u64 b = ((const u64*)bias0s)[l * 8 + hp];
            acc0[0][hp] = b; acc0[1][hp] = b;
        }
        #pragma unroll
        for (int j = 0; j < 8; ++j) {
            u64 dA = pack2(xa[j], xa[j]);
            u64 dB = pack2(xb[j], xb[j]);
            const ulonglong2* wrow = (const ulonglong2*)(w0ps + l * 128 + j * 16);
            #pragma unroll
            for (int hq = 0; hq < 4; ++hq) {
                ulonglong2 w = wrow[hq];                 // broadcast
                acc0[0][hq*2]   = ffma2(dA, w.x, acc0[0][hq*2]);
                acc0[0][hq*2+1] = ffma2(dA, w.y, acc0[0][hq*2+1]);
                acc0[1][hq*2]   = ffma2(dB, w.x, acc0[1][hq*2]);
                acc0[1][hq*2+1] = ffma2(dB, w.y, acc0[1][hq*2+1]);
            }
        }

        // tanh(h0/2) -> accumulate into h1; tanh first, weights streamed
        #pragma unroll
        for (int hp = 0; hp < 8; ++hp) {
            u64 dk0[2], dk1[2];
            #pragma unroll
            for (int r = 0; r < 2; ++r) {
                float a0, a1; unpack2(acc0[r][hp], a0, a1);
                float t0 = tanhap(a0), t1 = tanhap(a1);
                dk0[r] = pack2(t0, t0); dk1[r] = pack2(t1, t1);
            }
            const int k0 = l * 16 + hp * 2;
            const ulonglong2* wr0 = (const ulonglong2*)(w1s + k0 * 16);
            const ulonglong2* wr1 = (const ulonglong2*)(w1s + (k0 + 1) * 16);
            #pragma unroll
            for (int c = 0; c < 4; ++c) {
                ulonglong2 A = wr0[c];
                ulonglong2 B = wr1[c];
                #pragma unroll
                for (int r = 0; r < 2; ++r) {
                    acc1[r][c*2]   = ffma2(dk0[r], A.x, acc1[r][c*2]);
                    acc1[r][c*2+1] = ffma2(dk0[r], A.y, acc1[r][c*2+1]);
                    acc1[r][c*2]   = ffma2(dk1[r], B.x, acc1[r][c*2]);
                    acc1[r][c*2+1] = ffma2(dk1[r], B.y, acc1[r][c*2+1]);
                }
            }
        }
    }

    // finalize h1: exact sigmoid, store transposed fp16 (coalesced per warp)
    #pragma unroll
    for (int r = 0; r < 2; ++r) {
        const int row = r ? rB : rA;
        #pragma unroll
        for (int hp = 0; hp < 8; ++hp) {
            u64 s = sig2s(acc1[r][hp]);
            float s0, s1; unpack2(s, s0, s1);
            g_h1h[(size_t)(g * 16 + hp * 2)     * 4096 + row] = __float2half(s0);
            g_h1h[(size_t)(g * 16 + hp * 2 + 1) * 4096 + row] = __float2half(s1);
        }
    }
}

// ---------------------------------------------------------------------------
// K2 (R11 exact + PDL sync): grid 256 x 16 rows, 512 threads = 16 warps.
// warp w: module m=w&7, feature half (w>>3)*64. lane: row=lane&15,
// feature parity p=lane>>4 (32 features each, stride 2). shfl_xor(16) combine.
// ---------------------------------------------------------------------------
#define H2S_FLOATS (16 * 129 + 4)

__global__ __launch_bounds__(512, 2) void k2(
    const float* __restrict__ W2, const float* __restrict__ W3,
    const float* __restrict__ Wf, float* __restrict__ out)
{
    extern __shared__ __align__(16) unsigned char smraw2[];
    float* w2s   = (float*)smraw2;             // [m][k][h] * SCALE, 16384 f
    float* w3s   = w2s + 16384;                // [k][h]  * SCALE, 2048 f
    float* h2s   = w3s + 2048;                 // [row][129]
    u64*   part2 = (u64*)(h2s + H2S_FLOATS);   // [hp][m][row] = 8*8*16
    u64*   part  = part2 + 1024;               // [hp][w][row] = 8*8*16
    float* fpart = (float*)(part + 1024);      // [w][row] = 8*16

    const int tid  = threadIdx.x;
    const int warp = tid >> 5;
    const int lane = tid & 31;
    const int row  = lane & 15;
    const int par  = lane >> 4;
    const int row0 = blockIdx.x * 16;
    const int m    = warp & 7;
    const int fb   = m * 128 + (warp >> 3) * 64 + par;   // feature base, stride 2

    // stage W2, W3 (independent of k1's output — runs under PDL overlap)
    #pragma unroll
    for (int it = 0; it < 8; ++it) {
        int i4 = tid + 512 * it;               // 4096 float4
        float4 v = ((const float4*)W2)[i4];
        float4 o; o.x = v.x * SCALE; o.y = v.y * SCALE; o.z = v.z * SCALE; o.w = v.w * SCALE;
        ((float4*)w2s)[i4] = o;
    }
    {
        float4 v = ((const float4*)W3)[tid];   // 512 float4
        float4 o; o.x = v.x * SCALE; o.y = v.y * SCALE; o.z = v.z * SCALE; o.w = v.w * SCALE;
        ((float4*)w3s)[tid] = o;
    }
    __syncthreads();

    // wait for k1 to fully complete before touching g_h1h
    cudaGridDependencySynchronize();

    u64 acc[8];
    #pragma unroll
    for (int hp = 0; hp < 8; ++hp) acc[hp] = 0ull;
    {
        const __half* actc = g_h1h + (size_t)fb * 4096 + row0 + row;
        const float* wbase = w2s + fb * 16;

        float cur[8], nxt[8];
        #pragma unroll
        for (int t = 0; t < 8; ++t)
            cur[t] = __half2float(__ldg(actc + (size_t)(2 * t) * 4096));

        #pragma unroll
        for (int b = 0; b < 4; ++b) {
            if (b < 3) {
                #pragma unroll
                for (int t = 0; t < 8; ++t)
                    nxt[t] = __half2float(
                        __ldg(actc + (size_t)(2 * ((b + 1) * 8 + t)) * 4096));
            }
            #pragma unroll
            for (int t = 0; t < 8; ++t) {
                u64 d = pack2(cur[t], cur[t]);
                const ulonglong2* wr =
                    (const ulonglong2*)(wbase + 2 * (b * 8 + t) * 16);
                ulonglong2 w0 = wr[0], w1 = wr[1], w2v = wr[2], w3v = wr[3];
                acc[0] = ffma2(d, w0.x,  acc[0]);
                acc[1] = ffma2(d, w0.y,  acc[1]);
                acc[2] = ffma2(d, w1.x,  acc[2]);
                acc[3] = ffma2(d, w1.y,  acc[3]);
                acc[4] = ffma2(d, w2v.x, acc[4]);
                acc[5] = ffma2(d, w2v.y, acc[5]);
                acc[6] = ffma2(d, w3v.x, acc[6]);
                acc[7] = ffma2(d, w3v.y, acc[7]);
            }
            #pragma unroll
            for (int t = 0; t < 8; ++t) cur[t] = nxt[t];
        }
    }
    #pragma unroll
    for (int hp = 0; hp < 8; ++hp)
        acc[hp] = add2(acc[hp], __shfl_xor_sync(0xffffffffu, acc[hp], 16));

    if (warp >= 8 && par == 0) {
        #pragma unroll
        for (int hp = 0; hp < 8; ++hp)
            part2[hp * 128 + m * 16 + row] = acc[hp];
    }
    __syncthreads();

    if (warp < 8 && par == 0) {
        #pragma unroll
        for (int hp = 0; hp < 8; ++hp) {
            u64 s = sig2s(add2(acc[hp], part2[hp * 128 + m * 16 + row]));
            float s0, s1; unpack2(s, s0, s1);
            h2s[row * 129 + m * 16 + hp * 2]     = s0;
            h2s[row * 129 + m * 16 + hp * 2 + 1] = s1;
        }
    }
    __syncthreads();

    if (warp < 8) {
        u64 racc[8];
        #pragma unroll
        for (int hp = 0; hp < 8; ++hp) racc[hp] = 0ull;
        #pragma unroll
        for (int jj = 0; jj < 16; ++jj) {
            int jg = warp * 16 + jj;
            float a = h2s[row * 129 + jg];
            u64 d = pack2(a, a);
            const ulonglong2* wr = (const ulonglong2*)(w3s + jg * 16);
            ulonglong2 w0 = wr[0], w1 = wr[1], w2v = wr[2], w3v = wr[3];
            racc[0] = ffma2(d, w0.x,  racc[0]);
            racc[1] = ffma2(d, w0.y,  racc[1]);
            racc[2] = ffma2(d, w1.x,  racc[2]);
            racc[3] = ffma2(d, w1.y,  racc[3]);
            racc[4] = ffma2(d, w2v.x, racc[4]);
            racc[5] = ffma2(d, w2v.y, racc[5]);
            racc[6] = ffma2(d, w3v.x, racc[6]);
            racc[7] = ffma2(d, w3v.y, racc[7]);
        }
        if (par == 0) {
            #pragma unroll
            for (int hp = 0; hp < 8; ++hp)
                part[hp * 128 + warp * 16 + row] = racc[hp];
        }
    }
    __syncthreads();

    if (warp < 8 && par == 0) {
        u64 s = part[warp * 128 + row];
        #pragma unroll
        for (int ww = 1; ww < 8; ++ww)
            s = add2(s, part[warp * 128 + ww * 16 + row]);
        u64 sg = sig2s(s);
        float s0, s1; unpack2(sg, s0, s1);
        float c = s0 * __ldg(Wf + warp * 2) + s1 * __ldg(Wf + warp * 2 + 1);
        fpart[warp * 16 + row] = c;
    }
    __syncthreads();

    if (warp == 0 && par == 0) {
        float a = fpart[row];
        #pragma unroll
        for (int ww = 1; ww < 8; ++ww) a += fpart[ww * 16 + row];
        out[row0 + row] = a;
    }
}

static const int K2_SMEM = (16384 + 2048 + H2S_FLOATS) * 4 + 1024 * 8 + 1024 * 8 + 128 * 4;

extern "C" void kernel_launch(void* const* d_in, const int* in_sizes, int n_in,
                              void* d_out, int out_size)
{
    const float* x  = (const float*)d_in[0];
    const float* Wg = (const float*)d_in[1];
    const float* bg = (const float*)d_in[2];
    const float* W0 = (const float*)d_in[3];
    const float* W1 = (const float*)d_in[4];
    const float* W2 = (const float*)d_in[5];
    const float* W3 = (const float*)d_in[6];
    const float* Wf = (const float*)d_in[7];
    float* out = (float*)d_out;

    cudaFuncSetAttribute(k2, cudaFuncAttributeMaxDynamicSharedMemorySize, K2_SMEM);

    dim3 g1(16, 64);
    k1<<<g1, 128>>>(x, Wg, bg, W0, W1);

    // k2 with programmatic dependent launch: stages weights during k1's tail,
    // then cudaGridDependencySynchronize() gates the g_h1h reads.
    cudaLaunchConfig_t cfg = {};
    cfg.gridDim = dim3(256, 1, 1);
    cfg.blockDim = dim3(512, 1, 1);
    cfg.dynamicSmemBytes = (size_t)K2_SMEM;
    cfg.stream = 0;
    cudaLaunchAttribute attrs[1];
    attrs[0].id = cudaLaunchAttributeProgrammaticStreamSerialization;
    attrs[0].val.programmaticStreamSerializationAllowed = 1;
    cfg.attrs = attrs;
    cfg.numAttrs = 1;
    cudaLaunchKernelEx(&cfg, k2, W2, W3, Wf, out);
}

// round 16
// speedup vs baseline: 1.1833x; 1.1553x over previous
#include <cuda_runtime.h>
#include <cuda_fp16.h>

// RestrictedNN GB300. B=4096, NINP=4096, L0=512(G=8,H=16), L1=64, L2=8.
// k1: h0 scalar f32x2 (R11 exact) -> tanh -> fp16 swizzled smem tile ->
//     ldmatrix + mma.sync m16n8k16 for the h1 GEMM (C = SCALE*z1 in f32),
//     exact ex2/rcp sigmoid, stored transposed fp16 g_h1h[feature][row].
// k2: R11 exact.

#define SCALE (-1.44269504f)

typedef unsigned long long u64;
typedef unsigned int u32;

__device__ __half g_h1h[(size_t)1024 * 4096];   // [feature][row], 8 MB

__device__ __forceinline__ u64 pack2(float lo, float hi) {
    u64 r; asm("mov.b64 %0, {%1, %2};" : "=l"(r) : "f"(lo), "f"(hi)); return r;
}
__device__ __forceinline__ void unpack2(u64 v, float& lo, float& hi) {
    asm("mov.b64 {%0, %1}, %2;" : "=f"(lo), "=f"(hi) : "l"(v));
}
__device__ __forceinline__ u64 ffma2(u64 a, u64 b, u64 c) {
    u64 d; asm("fma.rn.f32x2 %0, %1, %2, %3;" : "=l"(d) : "l"(a), "l"(b), "l"(c));
    return d;
}
__device__ __forceinline__ u64 add2(u64 a, u64 b) {
    u64 d; asm("add.rn.f32x2 %0, %1, %2;" : "=l"(d) : "l"(a), "l"(b));
    return d;
}
__device__ __forceinline__ float tanhap(float z) {
    float t; asm("tanh.approx.f32 %0, %1;" : "=f"(t) : "f"(z)); return t;
}
__device__ __forceinline__ u64 sig2s(u64 z) {          // z pre-scaled by -log2e
    float a, b; unpack2(z, a, b);
    float ea, eb, ra, rb;
    asm("ex2.approx.f32 %0, %1;" : "=f"(ea) : "f"(a));
    asm("ex2.approx.f32 %0, %1;" : "=f"(eb) : "f"(b));
    asm("rcp.approx.f32 %0, %1;" : "=f"(ra) : "f"(1.0f + ea));
    asm("rcp.approx.f32 %0, %1;" : "=f"(rb) : "f"(1.0f + eb));
    return pack2(ra, rb);
}
__device__ __forceinline__ void mma16816(float* c, u32 a0, u32 a1, u32 a2, u32 a3,
                                         u32 b0, u32 b1) {
    asm volatile(
        "mma.sync.aligned.m16n8k16.row.col.f32.f16.f16.f32 "
        "{%0,%1,%2,%3},{%4,%5,%6,%7},{%8,%9},{%0,%1,%2,%3};"
        : "+f"(c[0]), "+f"(c[1]), "+f"(c[2]), "+f"(c[3])
        : "r"(a0), "r"(a1), "r"(a2), "r"(a3), "r"(b0), "r"(b1));
}

// swizzled chunk index (16B chunks) for a 64x16-half tile with 32B rows:
// chunk(r, cb) = 16*(r>>3) + ((2*(r&7)+cb) ^ (r&7))   -- bijective, ldmatrix-clean
__device__ __forceinline__ int swz(int r, int cb) {
    int b = r & 7;
    return 16 * (r >> 3) + ((2 * b + cb) ^ b);
}

// ---------------------------------------------------------------------------
// K1: grid (8 tile-groups, 64 g), 256 threads = 8 warps; warp -> one 64-row
// tile. Lane p handles rows (tile*64+p, tile*64+p+32) in h0; mma for h1.
// ---------------------------------------------------------------------------
__global__ __launch_bounds__(256, 2) void k1(
    const float* __restrict__ x, const float* __restrict__ Wg,
    const float* __restrict__ bgp, const float* __restrict__ W0,
    const float* __restrict__ W1)
{
    __shared__ __align__(16) float  w0ps[1024];     // [l][j][h] * Wg * 0.5
    __shared__ __align__(16) float  bias0s[128];    // [l][h] * 0.5
    __shared__ __align__(16) __half w1T[16 * 136];  // [h][k] * 0.5*SCALE, pad 136
    __shared__ __align__(16) float  bias1f[16];     // 0.5*SCALE*sum_k W1[k][h]
    __shared__ __align__(16) char   h0t[8 * 2 * 2048];  // per-warp dbl-buf tiles

    const int g   = blockIdx.y;
    const int tid = threadIdx.x;

    {
        float4 v = ((const float4*)(W0 + (size_t)g * 1024))[tid];
        float wg = Wg[g * 64 + (tid >> 2)] * 0.5f;
        float4 o; o.x = v.x * wg; o.y = v.y * wg; o.z = v.z * wg; o.w = v.w * wg;
        ((float4*)w0ps)[tid] = o;
    }
    #pragma unroll
    for (int it = 0; it < 8; ++it) {
        int idx = tid + 256 * it;                  // 2048 elems of W1[g]
        int k = idx >> 4, h = idx & 15;
        w1T[h * 136 + k] =
            __float2half(W1[(size_t)g * 2048 + idx] * (0.5f * SCALE));
    }
    if (tid < 128) {
        int l = tid >> 4, h = tid & 15;
        const float* bgl = bgp + g * 64 + l * 8;
        const float* w0l = W0 + (size_t)g * 1024 + l * 128 + h;
        float a = 0.f;
        #pragma unroll
        for (int j = 0; j < 8; ++j) a += bgl[j] * w0l[j * 16];
        bias0s[tid] = a * 0.5f;
    }
    __syncthreads();
    if (tid < 16) {
        float a = 0.f;
        for (int k = 0; k < 128; ++k) a += __half2float(w1T[tid * 136 + k]);
        bias1f[tid] = a;                           // already scaled
    }
    __syncthreads();

    const int warp = tid >> 5, lane = tid & 31;
    const int tile = blockIdx.x * 8 + warp;
    const int rA = tile * 64 + lane;
    const int rB = rA + 32;
    const float* xA = x + (size_t)rA * 4096 + g * 64;
    const float* xB = x + (size_t)rB * 4096 + g * 64;

    const int g_ = lane >> 2, t_ = lane & 3;
    // ldmatrix lane geometry: quadrants m0..m3 of each 16x16 A tile
    const int lrow = (lane & 7) + ((lane >> 3) & 1) * 8;
    const int lcb  = lane >> 4;
    const int ldoff = swz(lrow, lcb) * 16;         // + rt*512 per row-tile
    // STS geometry (row=lane and row=lane+32, both cb variants)
    const int sA0 = swz(lane, 0) * 16,      sA1 = swz(lane, 1) * 16;
    const int sB0 = swz(lane + 32, 0) * 16, sB1 = swz(lane + 32, 1) * 16;
    char* wbuf = h0t + warp * 4096;
    const u32 wbuf32 = (u32)__cvta_generic_to_shared(wbuf);

    // h1 accumulators: C[rt][nt][4], init from bias1
    float C[4][2][4];
    #pragma unroll
    for (int rt = 0; rt < 4; ++rt)
        #pragma unroll
        for (int nt = 0; nt < 2; ++nt) {
            float b0 = bias1f[nt * 8 + 2 * t_];
            float b1 = bias1f[nt * 8 + 2 * t_ + 1];
            C[rt][nt][0] = b0; C[rt][nt][1] = b1;
            C[rt][nt][2] = b0; C[rt][nt][3] = b1;
        }

    float4 pa0 = __ldg((const float4*)xA), pa1 = __ldg((const float4*)xA + 1);
    float4 pb0 = __ldg((const float4*)xB), pb1 = __ldg((const float4*)xB + 1);

    #pragma unroll 1
    for (int l = 0; l < 8; ++l) {
        float xa[8], xb[8];
        xa[0]=pa0.x; xa[1]=pa0.y; xa[2]=pa0.z; xa[3]=pa0.w;
        xa[4]=pa1.x; xa[5]=pa1.y; xa[6]=pa1.z; xa[7]=pa1.w;
        xb[0]=pb0.x; xb[1]=pb0.y; xb[2]=pb0.z; xb[3]=pb0.w;
        xb[4]=pb1.x; xb[5]=pb1.y; xb[6]=pb1.z; xb[7]=pb1.w;
        {
            int ln = (l + 1) & 7;
            pa0 = __ldg((const float4*)(xA + ln * 8));
            pa1 = __ldg((const float4*)(xA + ln * 8) + 1);
            pb0 = __ldg((const float4*)(xB + ln * 8));
            pb1 = __ldg((const float4*)(xB + ln * 8) + 1);
        }

        // ---- h0 (R11 exact): acc0 = 0.5*z0 as h-pairs ----
        u64 acc0[2][8];
        #pragma unroll
        for (int hp = 0; hp < 8; ++hp) {
            u64 b = ((const u64*)bias0s)[l * 8 + hp];
            acc0[0][hp] = b; acc0[1][hp] = b;
        }
        #pragma unroll
        for (int j = 0; j < 8; ++j) {
            u64 dA = pack2(xa[j], xa[j]);
            u64 dB = pack2(xb[j], xb[j]);
            const ulonglong2* wrow = (const ulonglong2*)(w0ps + l * 128 + j * 16);
            #pragma unroll
            for (int hq = 0; hq < 4; ++hq) {
                ulonglong2 w = wrow[hq];                 // broadcast
                acc0[0][hq*2]   = ffma2(dA, w.x, acc0[0][hq*2]);
                acc0[0][hq*2+1] = ffma2(dA, w.y, acc0[0][hq*2+1]);
                acc0[1][hq*2]   = ffma2(dB, w.x, acc0[1][hq*2]);
                acc0[1][hq*2+1] = ffma2(dB, w.y, acc0[1][hq*2+1]);
            }
        }

        // ---- tanh -> fp16 half2, store to swizzled per-warp tile ----
        char* buf = wbuf + ((l & 1) << 11);
        #pragma unroll
        for (int hp = 0; hp < 8; ++hp) {
            float a0, a1; unpack2(acc0[0][hp], a0, a1);
            __half2 hA = __floats2half2_rn(tanhap(a0), tanhap(a1));
            float b0, b1; unpack2(acc0[1][hp], b0, b1);
            __half2 hB = __floats2half2_rn(tanhap(b0), tanhap(b1));
            const int off = (hp & 3) * 4;
            const int sa = (hp >> 2) ? sA1 : sA0;
            const int sb = (hp >> 2) ? sB1 : sB0;
            *(u32*)(buf + sa + off) = *reinterpret_cast<u32*>(&hA);
            *(u32*)(buf + sb + off) = *reinterpret_cast<u32*>(&hB);
        }
        __syncwarp();

        // ---- B fragments from w1T (perfectly banked LDS.32) ----
        u32 bfr[2][2];
        #pragma unroll
        for (int nt = 0; nt < 2; ++nt) {
            int bi = (nt * 8 + g_) * 136 + l * 16 + 2 * t_;
            bfr[nt][0] = *(const u32*)&w1T[bi];
            bfr[nt][1] = *(const u32*)&w1T[bi + 8];
        }

        // ---- ldmatrix A + mma per 16-row tile ----
        const u32 base32 = wbuf32 + ((l & 1) << 11) + ldoff;
        #pragma unroll
        for (int rt = 0; rt < 4; ++rt) {
            u32 a0, a1, a2, a3;
            asm volatile(
                "ldmatrix.sync.aligned.m8n8.x4.shared.b16 {%0,%1,%2,%3},[%4];"
                : "=r"(a0), "=r"(a1), "=r"(a2), "=r"(a3)
                : "r"(base32 + rt * 512));
            mma16816(C[rt][0], a0, a1, a2, a3, bfr[0][0], bfr[0][1]);
            mma16816(C[rt][1], a0, a1, a2, a3, bfr[1][0], bfr[1][1]);
        }
    }

    // ---- finalize h1: exact sigmoid (C = SCALE*z1), store transposed fp16 ----
    #pragma unroll
    for (int rt = 0; rt < 4; ++rt) {
        const int r0 = tile * 64 + rt * 16 + g_;
        #pragma unroll
        for (int nt = 0; nt < 2; ++nt) {
            const int f0 = g * 16 + nt * 8 + 2 * t_;
            u64 s = sig2s(pack2(C[rt][nt][0], C[rt][nt][1]));
            float s0, s1; unpack2(s, s0, s1);
            g_h1h[(size_t)f0       * 4096 + r0] = __float2half(s0);
            g_h1h[(size_t)(f0 + 1) * 4096 + r0] = __float2half(s1);
            s = sig2s(pack2(C[rt][nt][2], C[rt][nt][3]));
            unpack2(s, s0, s1);
            g_h1h[(size_t)f0       * 4096 + r0 + 8] = __float2half(s0);
            g_h1h[(size_t)(f0 + 1) * 4096 + r0 + 8] = __float2half(s1);
        }
    }
}

// ---------------------------------------------------------------------------
// K2 (R11 exact): grid 256 x 16 rows, 512 threads = 16 warps.
// ---------------------------------------------------------------------------
#define H2S_FLOATS (16 * 129 + 4)

__global__ __launch_bounds__(512, 2) void k2(
    const float* __restrict__ W2, const float* __restrict__ W3,
    const float* __restrict__ Wf, float* __restrict__ out)
{
    extern __shared__ __align__(16) unsigned char smraw2[];
    float* w2s   = (float*)smraw2;             // [m][k][h] * SCALE, 16384 f
    float* w3s   = w2s + 16384;                // [k][h]  * SCALE, 2048 f
    float* h2s   = w3s + 2048;                 // [row][129]
    u64*   part2 = (u64*)(h2s + H2S_FLOATS);   // [hp][m][row] = 8*8*16
    u64*   part  = part2 + 1024;               // [hp][w][row] = 8*8*16
    float* fpart = (float*)(part + 1024);      // [w][row] = 8*16

    const int tid  = threadIdx.x;
    const int warp = tid >> 5;
    const int lane = tid & 31;
    const int row  = lane & 15;
    const int par  = lane >> 4;
    const int row0 = blockIdx.x * 16;
    const int m    = warp & 7;
    const int fb   = m * 128 + (warp >> 3) * 64 + par;

    #pragma unroll
    for (int it = 0; it < 8; ++it) {
        int i4 = tid + 512 * it;               // 4096 float4
        float4 v = ((const float4*)W2)[i4];
        float4 o; o.x = v.x * SCALE; o.y = v.y * SCALE; o.z = v.z * SCALE; o.w = v.w * SCALE;
        ((float4*)w2s)[i4] = o;
    }
    {
        float4 v = ((const float4*)W3)[tid];   // 512 float4
        float4 o; o.x = v.x * SCALE; o.y = v.y * SCALE; o.z = v.z * SCALE; o.w = v.w * SCALE;
        ((float4*)w3s)[tid] = o;
    }
    __syncthreads();

    u64 acc[8];
    #pragma unroll
    for (int hp = 0; hp < 8; ++hp) acc[hp] = 0ull;
    {
        const __half* actc = g_h1h + (size_t)fb * 4096 + row0 + row;
        const float* wbase = w2s + fb * 16;

        float cur[8], nxt[8];
        #pragma unroll
        for (int t = 0; t < 8; ++t)
            cur[t] = __half2float(__ldg(actc + (size_t)(2 * t) * 4096));

        #pragma unroll
        for (int b = 0; b < 4; ++b) {
            if (b < 3) {
                #pragma unroll
                for (int t = 0; t < 8; ++t)
                    nxt[t] = __half2float(
                        __ldg(actc + (size_t)(2 * ((b + 1) * 8 + t)) * 4096));
            }
            #pragma unroll
            for (int t = 0; t < 8; ++t) {
                u64 d = pack2(cur[t], cur[t]);
                const ulonglong2* wr =
                    (const ulonglong2*)(wbase + 2 * (b * 8 + t) * 16);
                ulonglong2 w0 = wr[0], w1 = wr[1], w2v = wr[2], w3v = wr[3];
                acc[0] = ffma2(d, w0.x,  acc[0]);
                acc[1] = ffma2(d, w0.y,  acc[1]);
                acc[2] = ffma2(d, w1.x,  acc[2]);
                acc[3] = ffma2(d, w1.y,  acc[3]);
                acc[4] = ffma2(d, w2v.x, acc[4]);
                acc[5] = ffma2(d, w2v.y, acc[5]);
                acc[6] = ffma2(d, w3v.x, acc[6]);
                acc[7] = ffma2(d, w3v.y, acc[7]);
            }
            #pragma unroll
            for (int t = 0; t < 8; ++t) cur[t] = nxt[t];
        }
    }
    #pragma unroll
    for (int hp = 0; hp < 8; ++hp)
        acc[hp] = add2(acc[hp], __shfl_xor_sync(0xffffffffu, acc[hp], 16));

    if (warp >= 8 && par == 0) {
        #pragma unroll
        for (int hp = 0; hp < 8; ++hp)
            part2[hp * 128 + m * 16 + row] = acc[hp];
    }
    __syncthreads();

    if (warp < 8 && par == 0) {
        #pragma unroll
        for (int hp = 0; hp < 8; ++hp) {
            u64 s = sig2s(add2(acc[hp], part2[hp * 128 + m * 16 + row]));
            float s0, s1; unpack2(s, s0, s1);
            h2s[row * 129 + m * 16 + hp * 2]     = s0;
            h2s[row * 129 + m * 16 + hp * 2 + 1] = s1;
        }
    }
    __syncthreads();

    if (warp < 8) {
        u64 racc[8];
        #pragma unroll
        for (int hp = 0; hp < 8; ++hp) racc[hp] = 0ull;
        #pragma unroll
        for (int jj = 0; jj < 16; ++jj) {
            int jg = warp * 16 + jj;
            float a = h2s[row * 129 + jg];
            u64 d = pack2(a, a);
            const ulonglong2* wr = (const ulonglong2*)(w3s + jg * 16);
            ulonglong2 w0 = wr[0], w1 = wr[1], w2v = wr[2], w3v = wr[3];
            racc[0] = ffma2(d, w0.x,  racc[0]);
            racc[1] = ffma2(d, w0.y,  racc[1]);
            racc[2] = ffma2(d, w1.x,  racc[2]);
            racc[3] = ffma2(d, w1.y,  racc[3]);
            racc[4] = ffma2(d, w2v.x, racc[4]);
            racc[5] = ffma2(d, w2v.y, racc[5]);
            racc[6] = ffma2(d, w3v.x, racc[6]);
            racc[7] = ffma2(d, w3v.y, racc[7]);
        }
        if (par == 0) {
            #pragma unroll
            for (int hp = 0; hp < 8; ++hp)
                part[hp * 128 + warp * 16 + row] = racc[hp];
        }
    }
    __syncthreads();

    if (warp < 8 && par == 0) {
        u64 s = part[warp * 128 + row];
        #pragma unroll
        for (int ww = 1; ww < 8; ++ww)
            s = add2(s, part[warp * 128 + ww * 16 + row]);
        u64 sg = sig2s(s);
        float s0, s1; unpack2(sg, s0, s1);
        float c = s0 * __ldg(Wf + warp * 2) + s1 * __ldg(Wf + warp * 2 + 1);
        fpart[warp * 16 + row] = c;
    }
    __syncthreads();

    if (warp == 0 && par == 0) {
        float a = fpart[row];
        #pragma unroll
        for (int ww = 1; ww < 8; ++ww) a += fpart[ww * 16 + row];
        out[row0 + row] = a;
    }
}

static const int K2_SMEM = (16384 + 2048 + H2S_FLOATS) * 4 + 1024 * 8 + 1024 * 8 + 128 * 4;

extern "C" void kernel_launch(void* const* d_in, const int* in_sizes, int n_in,
                              void* d_out, int out_size)
{
    const float* x  = (const float*)d_in[0];
    const float* Wg = (const float*)d_in[1];
    const float* bg = (const float*)d_in[2];
    const float* W0 = (const float*)d_in[3];
    const float* W1 = (const float*)d_in[4];
    const float* W2 = (const float*)d_in[5];
    const float* W3 = (const float*)d_in[6];
    const float* Wf = (const float*)d_in[7];
    float* out = (float*)d_out;

    cudaFuncSetAttribute(k2, cudaFuncAttributeMaxDynamicSharedMemorySize, K2_SMEM);

    dim3 g1(8, 64);
    k1<<<g1, 256>>>(x, Wg, bg, W0, W1);
    k2<<<256, 512, K2_SMEM>>>(W2, W3, Wf, out);
}